// round 3
// baseline (speedup 1.0000x reference)
#include <cuda_runtime.h>
#include <math.h>
#include <stdint.h>

#define BATCH 64
#define SEQ   512
#define HIDDEN 300
#define UNITS 512
#define GATES 1536           // 3 * UNITS, gate order [z, r, h]

#define NBLK 128             // scan grid size (must be <= SM count, 1 CTA/SM)
#define HSP  516             // padded h row length in floats (512 + 4) -> conflict-free float4

// ---------------------------------------------------------------------------
// Scratch (device globals; no allocations allowed)
// ---------------------------------------------------------------------------
__device__ float g_xg[(size_t)SEQ * BATCH * GATES];   // 201 MB, reused by both layers
__device__ float g_y0[(size_t)SEQ * BATCH * UNITS];   // 67 MB, layer0 outputs [s][b][u]
__device__ float g_h[2][BATCH * UNITS];               // double-buffered hidden state
__device__ unsigned g_cnt = 0;                        // barrier counter (self-resets)
__device__ volatile unsigned g_sense = 0;             // barrier sense (persists, sense-reversing)

// ---------------------------------------------------------------------------
// GEMM: C[m][n] = sum_k A[m][k] * W[k][n] + bias[n]
//   m = s*64 + b  (32768 rows), n in [0,1536)
//   gather=1: A row = emb[tokens[b][s]]  (K=300)
//   gather=0: A row = A + m*K            (K=512)
// ---------------------------------------------------------------------------
__global__ void __launch_bounds__(256) gemm_bias(
    const float* __restrict__ A, const int* __restrict__ tokens,
    const float* __restrict__ emb, const float* __restrict__ W,
    const float* __restrict__ bias, float* __restrict__ C,
    int K, int gather)
{
    const int N = GATES;
    __shared__ float As[16][65];   // [k][m], padded
    __shared__ float Bs[16][64];   // [k][n]

    const int tx = threadIdx.x & 15;
    const int ty = threadIdx.x >> 4;
    const int m0 = blockIdx.y * 64;
    const int n0 = blockIdx.x * 64;

    float acc[4][4] = {};

    const int ntiles = (K + 15) >> 4;
    for (int kt = 0; kt < ntiles; kt++) {
        const int k0 = kt << 4;
#pragma unroll
        for (int i = 0; i < 4; i++) {
            int idx = threadIdx.x + i * 256;
            // A tile: idx -> (mm, kk); consecutive threads read consecutive k
            int mm = idx >> 4, kk = idx & 15;
            int m = m0 + mm, k = k0 + kk;
            const float* arow;
            if (gather) {
                int tok = tokens[(m & 63) * SEQ + (m >> 6)];
                arow = emb + (size_t)tok * HIDDEN;
            } else {
                arow = A + (size_t)m * K;
            }
            As[kk][mm] = (k < K) ? arow[k] : 0.f;
            // B tile: idx -> (k2, nn); consecutive threads read consecutive n
            int nn = idx & 63, k2 = idx >> 6;
            int kg = k0 + k2;
            Bs[k2][nn] = (kg < K) ? W[(size_t)kg * N + n0 + nn] : 0.f;
        }
        __syncthreads();
#pragma unroll
        for (int kk = 0; kk < 16; kk++) {
            float a[4], b[4];
#pragma unroll
            for (int i = 0; i < 4; i++) a[i] = As[kk][ty * 4 + i];
#pragma unroll
            for (int j = 0; j < 4; j++) b[j] = Bs[kk][tx * 4 + j];
#pragma unroll
            for (int i = 0; i < 4; i++)
#pragma unroll
                for (int j = 0; j < 4; j++)
                    acc[i][j] = fmaf(a[i], b[j], acc[i][j]);
        }
        __syncthreads();
    }

#pragma unroll
    for (int i = 0; i < 4; i++) {
        int m = m0 + ty * 4 + i;
#pragma unroll
        for (int j = 0; j < 4; j++) {
            int n = n0 + tx * 4 + j;
            C[(size_t)m * N + n] = acc[i][j] + bias[n];
        }
    }
}

// ---------------------------------------------------------------------------
// Grid barrier: sense-reversing, self-resetting (safe across graph replays).
// All threads fence first so every thread's .cg stores are globally visible
// before the release on g_sense.
// ---------------------------------------------------------------------------
__device__ __forceinline__ void grid_barrier(unsigned& local)
{
    __threadfence();
    __syncthreads();
    if (threadIdx.x == 0) {
        unsigned s = local ^ 1u;
        local = s;
        if (atomicAdd(&g_cnt, 1u) == (unsigned)(NBLK - 1)) {
            g_cnt = 0;             // safe: all arrived; next use is after sense flip
            __threadfence();
            g_sense = s;           // release
        } else {
            while (g_sense != s) __nanosleep(64);
            __threadfence();       // acquire-ish
        }
    }
    __syncthreads();
}

// ---------------------------------------------------------------------------
// Persistent GRU scan. Grid = 128 CTAs x 256 threads (1 CTA/SM guaranteed by
// 128KB smem -> all co-resident, barrier is deadlock-free).
//   CTA c: batch group bg = c>>5 (16 batches), column group jg = c&31 (16 h-cols).
//   smem: Us[48 gate-cols][512 k] (96KB) + hs[16 batch][516] (32.25KB).
// Per step: rg = h @ U (+b[1]) for owned columns, gates, h_new; grid sync; restage h.
// ---------------------------------------------------------------------------
__global__ void __launch_bounds__(256, 1) gru_scan(
    const float* __restrict__ U,      // [512][1536]
    const float* __restrict__ brec,   // recurrent bias b[1], length 1536
    const float* __restrict__ xg,     // [SEQ][BATCH][1536] (input proj + b[0])
    float* __restrict__ y,            // layer0: [s][b][512]; layer1: [b][s][512]
    float* __restrict__ hlast,        // layer1 only
    int layer)
{
    extern __shared__ float sm[];
    float* Us = sm;                   // 48*512 floats
    float* hs = sm + 48 * 512;        // 16*HSP floats

    const int tid = threadIdx.x;
    const int c = blockIdx.x;
    const int bg = c >> 5;            // 0..3
    const int jg = c & 31;            // 0..31

    // Load this CTA's U slice: Us[(g*16+cc)][k] = U[k][g*512 + jg*16 + cc]
    for (int idx = tid; idx < 48 * 512; idx += 256) {
        int cg = idx >> 9, k = idx & 511;
        int g = cg >> 4, cc2 = cg & 15;
        Us[idx] = __ldg(&U[(size_t)k * GATES + g * UNITS + jg * 16 + cc2]);
    }

    const int cc = tid >> 4;          // 0..15 : local column
    const int bl = tid & 15;          // 0..15 : local batch
    const int jglob = jg * 16 + cc;   // 0..511
    const int bglob = bg * 16 + bl;   // 0..63

    const float bz = brec[jglob];
    const float br = brec[UNITS + jglob];
    const float bh = brec[2 * UNITS + jglob];

    // h0 = 0 (local staging only; global buffers are written before ever read)
    for (int idx = tid; idx < 16 * HSP; idx += 256) hs[idx] = 0.f;

    unsigned local = g_sense;         // safe: no flip can occur before all CTAs arrive at bar 1
    __syncthreads();

    const float4* uz = (const float4*)(Us + (0 * 16 + cc) * 512);
    const float4* ur = (const float4*)(Us + (1 * 16 + cc) * 512);
    const float4* uh = (const float4*)(Us + (2 * 16 + cc) * 512);
    const float4* hp = (const float4*)(hs + bl * HSP);

    for (int t = 0; t < SEQ; t++) {
        // issue xg + h_old loads early (independent of the dot) for latency overlap
        const float* xgp = xg + ((size_t)t * BATCH + bglob) * GATES;
        float xz = __ldcg(xgp + jglob);
        float xr = __ldcg(xgp + UNITS + jglob);
        float xh = __ldcg(xgp + 2 * UNITS + jglob);
        float hold = hs[bl * HSP + jglob];

        float az = 0.f, ar = 0.f, ah = 0.f;
#pragma unroll 4
        for (int kk = 0; kk < 128; kk++) {
            float4 h4 = hp[kk];
            float4 u0 = uz[kk];
            float4 u1 = ur[kk];
            float4 u2 = uh[kk];
            az = fmaf(h4.x, u0.x, az); az = fmaf(h4.y, u0.y, az);
            az = fmaf(h4.z, u0.z, az); az = fmaf(h4.w, u0.w, az);
            ar = fmaf(h4.x, u1.x, ar); ar = fmaf(h4.y, u1.y, ar);
            ar = fmaf(h4.z, u1.z, ar); ar = fmaf(h4.w, u1.w, ar);
            ah = fmaf(h4.x, u2.x, ah); ah = fmaf(h4.y, u2.y, ah);
            ah = fmaf(h4.z, u2.z, ah); ah = fmaf(h4.w, u2.w, ah);
        }

        float z = 1.f / (1.f + expf(-(xz + az + bz)));
        float r = 1.f / (1.f + expf(-(xr + ar + br)));
        float hhat = tanhf(xh + r * (ah + bh));
        float hnew = z * hold + (1.f - z) * hhat;

        const int nb = (t + 1) & 1;
        __stcg(&g_h[nb][bglob * UNITS + jglob], hnew);
        if (layer == 0) {
            __stcg(&y[((size_t)t * BATCH + bglob) * UNITS + jglob], hnew);
        } else {
            __stcg(&y[((size_t)bglob * SEQ + t) * UNITS + jglob], hnew);
            if (t == SEQ - 1) __stcg(&hlast[bglob * UNITS + jglob], hnew);
        }

        grid_barrier(local);

        // restage h for next step (bypass L1: written by other SMs)
        const float4* gsrc = (const float4*)(&g_h[nb][bg * 16 * UNITS]);
        float4* hsd = (float4*)hs;
        for (int idx = tid; idx < 16 * 128; idx += 256) {
            int b2 = idx >> 7, k2 = idx & 127;
            hsd[b2 * 129 + k2] = __ldcg(gsrc + b2 * 128 + k2);
        }
        __syncthreads();
    }
}

// ---------------------------------------------------------------------------
// Launch
// ---------------------------------------------------------------------------
extern "C" void kernel_launch(void* const* d_in, const int* in_sizes, int n_in,
                              void* d_out, int out_size)
{
    const int*   tokens = (const int*)d_in[0];
    const float* emb    = (const float*)d_in[1];
    const float* W0     = (const float*)d_in[2];
    const float* U0     = (const float*)d_in[3];
    const float* b0     = (const float*)d_in[4];
    const float* W1     = (const float*)d_in[5];
    const float* U1     = (const float*)d_in[6];
    const float* b1     = (const float*)d_in[7];

    float* out = (float*)d_out;
    float* y1  = out;                                    // [64][512][512]
    float* h1  = out + (size_t)BATCH * SEQ * UNITS;      // [64][512]

    float *xg, *y0;
    cudaGetSymbolAddress((void**)&xg, g_xg);
    cudaGetSymbolAddress((void**)&y0, g_y0);

    const int smem_scan = (48 * 512 + 16 * HSP) * (int)sizeof(float); // 131328 B
    cudaFuncSetAttribute(gru_scan, cudaFuncAttributeMaxDynamicSharedMemorySize, smem_scan);

    dim3 ggrid(GATES / 64, (SEQ * BATCH) / 64);          // (24, 512)

    // Layer 0: xg = gather(emb, tokens) @ W0 + b0[0]
    gemm_bias<<<ggrid, 256>>>(nullptr, tokens, emb, W0, b0, xg, HIDDEN, 1);
    // Layer 0 scan -> y0 [s][b][u]
    gru_scan<<<NBLK, 256, smem_scan>>>(U0, b0 + GATES, xg, y0, nullptr, 0);
    // Layer 1: xg = y0 @ W1 + b1[0]
    gemm_bias<<<ggrid, 256>>>(y0, nullptr, nullptr, W1, b1, xg, UNITS, 0);
    // Layer 1 scan -> y1 [b][s][u], h1
    gru_scan<<<NBLK, 256, smem_scan>>>(U1, b1 + GATES, xg, y1, h1, 1);
}

// round 4
// speedup vs baseline: 1.3361x; 1.3361x over previous
#include <cuda_runtime.h>
#include <math.h>
#include <stdint.h>

#define BATCH 64
#define SEQ   512
#define HIDDEN 300
#define UNITS 512
#define GATES 1536           // 3 * UNITS, gate order [z, r, h]

#define NBLK 128             // scan grid size (all CTAs co-resident)
#define CHW  34              // floats per 32-k h chunk (padded: 136B, 8B-aligned, bank-skewed)

typedef unsigned long long ull;

// ---------------------------------------------------------------------------
// Packed f32x2 helpers (sm_100+: FFMA2)
// ---------------------------------------------------------------------------
__device__ __forceinline__ void ffma2(ull& d, ull a, ull b) {
    asm("fma.rn.f32x2 %0, %1, %2, %0;" : "+l"(d) : "l"(a), "l"(b));
}
__device__ __forceinline__ ull pack2(float x, float y) {
    ull r; asm("mov.b64 %0, {%1, %2};" : "=l"(r) : "f"(x), "f"(y)); return r;
}
__device__ __forceinline__ float2 unpack2(ull v) {
    float2 r; asm("mov.b64 {%0, %1}, %2;" : "=f"(r.x), "=f"(r.y) : "l"(v)); return r;
}
__device__ __forceinline__ ull lds64(unsigned addr) {
    ull r; asm volatile("ld.shared.b64 %0, [%1];" : "=l"(r) : "r"(addr)); return r;
}
__device__ __forceinline__ unsigned smem_u32(const void* p) {
    return (unsigned)__cvta_generic_to_shared(p);
}

// ---------------------------------------------------------------------------
// Scratch (device globals; no allocations allowed)
// ---------------------------------------------------------------------------
__device__ float g_xg[(size_t)SEQ * BATCH * GATES];   // 201 MB, reused by both layers
__device__ float g_y0[(size_t)SEQ * BATCH * UNITS];   // 67 MB, layer0 outputs [s][b][u]
__device__ float g_h[2][BATCH * UNITS];               // double-buffered hidden state
__device__ unsigned g_cnt = 0;                        // barrier counter (self-resets)
__device__ volatile unsigned g_sense = 0;             // barrier sense (sense-reversing)

// ---------------------------------------------------------------------------
// GEMM: C[m][n] = sum_k A[m][k] * W[k][n] + bias[n]
//   m = s*64 + b (32768 rows), n in [0,1536). BM=128, BN=64, BK=16.
//   Thread computes 8x4 outputs as 4 f32x2 pairs along M.
//   gather=1: A row = emb[tokens[b][s]] (K=300); gather=0: A + m*K (K=512).
// ---------------------------------------------------------------------------
#define BM 128
#define BN 64
#define BK 16
__global__ void __launch_bounds__(256) gemm_bias(
    const float* __restrict__ A, const int* __restrict__ tokens,
    const float* __restrict__ emb, const float* __restrict__ W,
    const float* __restrict__ bias, float* __restrict__ C,
    int K, int gather)
{
    __shared__ float As[BK][132];   // [k][m] padded (528B rows: 8B aligned)
    __shared__ float Bs[BK][BN];    // [k][n]

    const int tid = threadIdx.x;
    const int tx = tid & 15;        // n group: cols tx*4 .. +4
    const int ty = tid >> 4;        // m group: rows ty*8 .. +8
    const int m0 = blockIdx.y * BM;
    const int n0 = blockIdx.x * BN;

    ull acc[4][4];
#pragma unroll
    for (int i = 0; i < 4; i++)
#pragma unroll
        for (int j = 0; j < 4; j++) acc[i][j] = 0ull;

    const unsigned asadr = smem_u32(&As[0][0]);

    const int ntiles = (K + BK - 1) / BK;
    for (int kt = 0; kt < ntiles; kt++) {
        const int k0 = kt * BK;
        // Stage A tile: 2048 elems, 8 per thread (consecutive threads -> consecutive k)
#pragma unroll
        for (int i = 0; i < 8; i++) {
            int idx = tid + i * 256;
            int mm = idx >> 4, kk = idx & 15;
            int k = k0 + kk;
            const float* arow;
            if (gather) {
                int m = m0 + mm;
                int tok = __ldg(&tokens[(m & 63) * SEQ + (m >> 6)]);
                arow = emb + (size_t)tok * HIDDEN;
            } else {
                arow = A + (size_t)(m0 + mm) * K;
            }
            As[kk][mm] = (k < K) ? __ldg(&arow[k]) : 0.f;
        }
        // Stage B tile: 256 float4
        {
            int k2 = tid >> 4, nn4 = tid & 15;
            int kg = k0 + k2;
            float4 v = make_float4(0.f, 0.f, 0.f, 0.f);
            if (kg < K) v = *(const float4*)&W[(size_t)kg * GATES + n0 + nn4 * 4];
            *(float4*)&Bs[k2][nn4 * 4] = v;
        }
        __syncthreads();
#pragma unroll
        for (int kk = 0; kk < BK; kk++) {
            ull ap[4];
#pragma unroll
            for (int ip = 0; ip < 4; ip++)
                ap[ip] = lds64(asadr + (unsigned)((kk * 132 + ty * 8 + ip * 2) * 4));
            ull bd[4];
#pragma unroll
            for (int j = 0; j < 4; j++) {
                float b = Bs[kk][tx * 4 + j];
                bd[j] = pack2(b, b);
            }
#pragma unroll
            for (int ip = 0; ip < 4; ip++)
#pragma unroll
                for (int j = 0; j < 4; j++)
                    ffma2(acc[ip][j], ap[ip], bd[j]);
        }
        __syncthreads();
    }

    const float4 bv = *(const float4*)&bias[n0 + tx * 4];
#pragma unroll
    for (int ip = 0; ip < 4; ip++) {
        float4 lo4, hi4;
        float2 p;
        p = unpack2(acc[ip][0]); lo4.x = p.x + bv.x; hi4.x = p.y + bv.x;
        p = unpack2(acc[ip][1]); lo4.y = p.x + bv.y; hi4.y = p.y + bv.y;
        p = unpack2(acc[ip][2]); lo4.z = p.x + bv.z; hi4.z = p.y + bv.z;
        p = unpack2(acc[ip][3]); lo4.w = p.x + bv.w; hi4.w = p.y + bv.w;
        int m = m0 + ty * 8 + ip * 2;
        *(float4*)&C[(size_t)m * GATES + n0 + tx * 4] = lo4;
        *(float4*)&C[(size_t)(m + 1) * GATES + n0 + tx * 4] = hi4;
    }
}

// ---------------------------------------------------------------------------
// Grid barrier: sense-reversing, self-resetting (safe across graph replays).
// ---------------------------------------------------------------------------
__device__ __forceinline__ void grid_barrier(unsigned& local)
{
    __threadfence();
    __syncthreads();
    if (threadIdx.x == 0) {
        unsigned s = local ^ 1u;
        local = s;
        if (atomicAdd(&g_cnt, 1u) == (unsigned)(NBLK - 1)) {
            g_cnt = 0;
            __threadfence();
            g_sense = s;           // release
        } else {
            while (g_sense != s) { }
            __threadfence();
        }
    }
    __syncthreads();
}

// ---------------------------------------------------------------------------
// Persistent GRU scan. 128 CTAs x 256 threads.
//   CTA c: bg = c>>5 (16 batches), jg = c&31 (16 h-columns).
//   Thread (cc = tid>>4, kc = tid&15): owns output (b = bg*16+kc, j = jg*16+cc);
//   holds U[3][32] for column j, k-chunk kc in registers (packed f32x2).
//   Per step: 16-way k-split dot over h (smem, bank-skewed chunks), butterfly
//   reduce over kc lanes, gate math, grid sync, restage h + stage xg.
// ---------------------------------------------------------------------------
__global__ void __launch_bounds__(256, 1) gru_scan(
    const float* __restrict__ U,      // [512][1536]
    const float* __restrict__ brec,   // recurrent bias b[1], length 1536
    const float* __restrict__ xg,     // [SEQ][BATCH][1536] (input proj + b[0])
    float* __restrict__ y,            // layer0: [s][b][512]; layer1: [b][s][512]
    float* __restrict__ hlast,        // layer1 only
    int layer)
{
    extern __shared__ float sm[];
    float* hs = sm;                   // 256 chunks * CHW floats = 8704
    float* xs = sm + 256 * CHW;       // 16 * 50 = 800

    const int tid = threadIdx.x;
    const int cc = tid >> 4;          // 0..15 : local column
    const int kc = tid & 15;          // 0..15 : k-chunk / owned local batch
    const int c = blockIdx.x;
    const int bg = c >> 5;            // 0..3
    const int jg = c & 31;            // 0..31
    const int jglob = jg * 16 + cc;
    const int bglob = bg * 16 + kc;

    // ---- Stage U into smem (coalesced 64B chunks), then lift to registers ----
    {
        float* Ustage = sm;           // [48 cols][512 k]
        for (int i = tid; i < 512 * 64; i += 256) {
            int c64 = i & 63;
            if (c64 < 48) {
                int k = i >> 6;
                int g = c64 >> 4, c2 = c64 & 15;
                Ustage[c64 * 512 + k] = __ldg(&U[(size_t)k * GATES + g * UNITS + jg * 16 + c2]);
            }
        }
        __syncthreads();
    }
    ull uz[16], ur[16], uh[16];
    {
        const float* Ustage = sm;
        const int k0 = kc * 32;
#pragma unroll
        for (int i = 0; i < 16; i++) {
            uz[i] = pack2(Ustage[(0 * 16 + cc) * 512 + k0 + 2 * i],
                          Ustage[(0 * 16 + cc) * 512 + k0 + 2 * i + 1]);
            ur[i] = pack2(Ustage[(1 * 16 + cc) * 512 + k0 + 2 * i],
                          Ustage[(1 * 16 + cc) * 512 + k0 + 2 * i + 1]);
            uh[i] = pack2(Ustage[(2 * 16 + cc) * 512 + k0 + 2 * i],
                          Ustage[(2 * 16 + cc) * 512 + k0 + 2 * i + 1]);
        }
    }
    const float bz = brec[jglob];
    const float br = brec[UNITS + jglob];
    const float bh = brec[2 * UNITS + jglob];
    __syncthreads();

    // h0 = 0
    for (int i = tid; i < 256 * CHW; i += 256) hs[i] = 0.f;

    unsigned local = g_sense;         // all CTAs read before any flip can occur
    const unsigned hsaddr = smem_u32(hs);
    float hold = 0.f;
    float AZ = 0.f, AR = 0.f, AH = 0.f;
    __syncthreads();

    for (int t = 0; t < SEQ; t++) {
        // Stage xg tile for this step: 768 floats, coalesced
        {
            const float* xb = xg + ((size_t)t * BATCH + bg * 16) * GATES;
#pragma unroll
            for (int p = 0; p < 3; p++) {
                int idx = tid + p * 256;            // 0..767
                int b = idx / 48, ccol = idx - b * 48;
                int g = ccol >> 4, c2 = ccol & 15;
                xs[b * 50 + ccol] = __ldcg(&xb[(size_t)b * GATES + g * UNITS + jg * 16 + c2]);
            }
        }
        __syncthreads();   // xs ready; also orders previous restage of hs

        // 16-way k-split dot + butterfly reduction over kc lanes
#pragma unroll 2
        for (int bl = 0; bl < 16; bl++) {
            const unsigned ha = hsaddr + (unsigned)((bl * 16 + kc) * (CHW * 4));
            ull az = 0ull, ar = 0ull, ah = 0ull;
#pragma unroll
            for (int i = 0; i < 16; i++) {
                ull hv = lds64(ha + (unsigned)(8 * i));
                ffma2(az, hv, uz[i]);
                ffma2(ar, hv, ur[i]);
                ffma2(ah, hv, uh[i]);
            }
            float2 a2 = unpack2(az); float azf = a2.x + a2.y;
            float2 r2 = unpack2(ar); float arf = r2.x + r2.y;
            float2 h2 = unpack2(ah); float ahf = h2.x + h2.y;
#pragma unroll
            for (int m = 1; m <= 8; m <<= 1) {
                azf += __shfl_xor_sync(0xffffffffu, azf, m);
                arf += __shfl_xor_sync(0xffffffffu, arf, m);
                ahf += __shfl_xor_sync(0xffffffffu, ahf, m);
            }
            if (bl == kc) { AZ = azf; AR = arf; AH = ahf; }
        }

        // Gate math (fast transcendentals; rel err ~1e-6)
        const float xz = xs[kc * 50 + cc];
        const float xr = xs[kc * 50 + 16 + cc];
        const float xh = xs[kc * 50 + 32 + cc];
        float z = __fdividef(1.f, 1.f + __expf(-(xz + AZ + bz)));
        float r = __fdividef(1.f, 1.f + __expf(-(xr + AR + br)));
        float pre = xh + r * (AH + bh);
        float hhat = 1.f - __fdividef(2.f, __expf(2.f * pre) + 1.f);  // tanh
        float hnew = z * hold + (1.f - z) * hhat;
        hold = hnew;

        const int nb = (t + 1) & 1;
        __stcg(&g_h[nb][bglob * UNITS + jglob], hnew);
        if (layer == 0) {
            __stcg(&y[((size_t)t * BATCH + bglob) * UNITS + jglob], hnew);
        } else {
            __stcg(&y[((size_t)bglob * SEQ + t) * UNITS + jglob], hnew);
            if (t == SEQ - 1) __stcg(&hlast[bglob * UNITS + jglob], hnew);
        }

        grid_barrier(local);

        // Restage h for next step (L2 path; other SMs wrote it)
        {
            const float2* gsrc = (const float2*)(&g_h[nb][bg * 16 * UNITS]);
#pragma unroll
            for (int p = 0; p < 16; p++) {
                int e2 = tid + p * 256;              // 0..4095 (float2 index)
                int b = e2 >> 8, kp = e2 & 255;
                float2 v = __ldcg(&gsrc[e2]);
                *(float2*)(hs + (b * 16 + (kp >> 4)) * CHW + (kp & 15) * 2) = v;
            }
        }
        // next iteration's __syncthreads (after xs staging) orders hs
    }
}

// ---------------------------------------------------------------------------
// Launch
// ---------------------------------------------------------------------------
extern "C" void kernel_launch(void* const* d_in, const int* in_sizes, int n_in,
                              void* d_out, int out_size)
{
    const int*   tokens = (const int*)d_in[0];
    const float* emb    = (const float*)d_in[1];
    const float* W0     = (const float*)d_in[2];
    const float* U0     = (const float*)d_in[3];
    const float* b0     = (const float*)d_in[4];
    const float* W1     = (const float*)d_in[5];
    const float* U1     = (const float*)d_in[6];
    const float* b1     = (const float*)d_in[7];

    float* out = (float*)d_out;
    float* y1  = out;                                    // [64][512][512]
    float* h1  = out + (size_t)BATCH * SEQ * UNITS;      // [64][512]

    float *xgp, *y0p;
    cudaGetSymbolAddress((void**)&xgp, g_xg);
    cudaGetSymbolAddress((void**)&y0p, g_y0);

    const int smem_scan = 48 * 512 * (int)sizeof(float); // 98304 B (U staging; >= hs+xs)
    cudaFuncSetAttribute(gru_scan, cudaFuncAttributeMaxDynamicSharedMemorySize, smem_scan);

    dim3 ggrid(GATES / BN, (SEQ * BATCH) / BM);          // (24, 256)

    // Layer 0: xg = gather(emb, tokens) @ W0 + b0[0]
    gemm_bias<<<ggrid, 256>>>(nullptr, tokens, emb, W0, b0, xgp, HIDDEN, 1);
    // Layer 0 scan -> y0 [s][b][u]
    gru_scan<<<NBLK, 256, smem_scan>>>(U0, b0 + GATES, xgp, y0p, nullptr, 0);
    // Layer 1: xg = y0 @ W1 + b1[0]
    gemm_bias<<<ggrid, 256>>>(y0p, nullptr, nullptr, W1, b1, xgp, UNITS, 0);
    // Layer 1 scan -> y1 [b][s][u], h1
    gru_scan<<<NBLK, 256, smem_scan>>>(U1, b1 + GATES, xgp, y1, h1, 1);
}

// round 6
// speedup vs baseline: 1.4157x; 1.0596x over previous
#include <cuda_runtime.h>
#include <math.h>
#include <stdint.h>

#define BATCH 64
#define SEQ   512
#define HIDDEN 300
#define UNITS 512
#define GATES 1536           // 3 * UNITS, gate order [z, r, h]

#define NBLK 128             // scan grid size (all CTAs co-resident)
#define CHW  34              // floats per 32-k h chunk (136B, 8B-aligned, bank-skewed)

typedef unsigned long long ull;

// ---------------------------------------------------------------------------
// Packed f32x2 helpers (sm_100+: FFMA2)
// ---------------------------------------------------------------------------
__device__ __forceinline__ void ffma2(ull& d, ull a, ull b) {
    asm("fma.rn.f32x2 %0, %1, %2, %0;" : "+l"(d) : "l"(a), "l"(b));
}
__device__ __forceinline__ ull pack2(float x, float y) {
    ull r; asm("mov.b64 %0, {%1, %2};" : "=l"(r) : "f"(x), "f"(y)); return r;
}
__device__ __forceinline__ float2 unpack2(ull v) {
    float2 r; asm("mov.b64 {%0, %1}, %2;" : "=f"(r.x), "=f"(r.y) : "l"(v)); return r;
}
__device__ __forceinline__ ull lds64(unsigned addr) {
    ull r; asm volatile("ld.shared.b64 %0, [%1];" : "=l"(r) : "r"(addr)); return r;
}
__device__ __forceinline__ unsigned smem_u32(const void* p) {
    return (unsigned)__cvta_generic_to_shared(p);
}
// One scatter-reduce step: lane keeps the slot matching its kc bit, sends the
// other; the single shfl serves both directions of the pair.
__device__ __forceinline__ float red_step(float e, float o, bool bit, int m) {
    float send = bit ? e : o;
    float keep = bit ? o : e;
    return keep + __shfl_xor_sync(0xffffffffu, send, m);
}

// ---------------------------------------------------------------------------
// Scratch (device globals; no allocations allowed)
// ---------------------------------------------------------------------------
__device__ float g_xg[(size_t)SEQ * BATCH * GATES];   // 201 MB, reused by both layers
__device__ float g_y0[(size_t)SEQ * BATCH * UNITS];   // 67 MB, layer0 outputs [s][b][u]
__device__ float g_h[2][BATCH * UNITS];               // double-buffered hidden state
__device__ unsigned g_cnt4[4];                        // per-bg barrier counters
__device__ volatile unsigned g_sense4[4];             // per-bg senses (self-restoring)

// ---------------------------------------------------------------------------
// GEMM: C[m][n] = sum_k A[m][k] * W[k][n] + bias[n]
//   m = s*64 + b (32768 rows), n in [0,1536). BM=128, BN=128, BK=16.
//   Thread tile 8x8 as 4 M-pairs (f32x2) x 8 N.
// ---------------------------------------------------------------------------
#define BM 128
#define BN 128
#define BK 16
__global__ void __launch_bounds__(256, 2) gemm_bias(
    const float* __restrict__ A, const int* __restrict__ tokens,
    const float* __restrict__ emb, const float* __restrict__ W,
    const float* __restrict__ bias, float* __restrict__ C,
    int K, int gather)
{
    __shared__ float As[BK][132];   // [k][m] padded
    __shared__ float Bs[BK][BN];
    __shared__ int   stok[BM];

    const int tid = threadIdx.x;
    const int tx = tid & 15;        // 8 cols: n0 + tx*8 ..
    const int ty = tid >> 4;        // 8 rows: m0 + ty*8 ..
    const int m0 = blockIdx.y * BM;
    const int n0 = blockIdx.x * BN;

    if (gather && tid < BM) {
        int m = m0 + tid;
        stok[tid] = __ldg(&tokens[(m & 63) * SEQ + (m >> 6)]);
    }
    __syncthreads();

    ull acc[4][8];
#pragma unroll
    for (int i = 0; i < 4; i++)
#pragma unroll
        for (int j = 0; j < 8; j++) acc[i][j] = 0ull;

    const unsigned asadr = smem_u32(&As[0][0]);

    const int ntiles = (K + BK - 1) / BK;
    for (int kt = 0; kt < ntiles; kt++) {
        const int k0 = kt * BK;
        // Stage A tile: 2048 elems, 8/thread (consecutive threads -> consecutive k)
#pragma unroll
        for (int i = 0; i < 8; i++) {
            int idx = tid + i * 256;
            int mm = idx >> 4, kk = idx & 15;
            int k = k0 + kk;
            const float* arow;
            if (gather) arow = emb + (size_t)stok[mm] * HIDDEN;
            else        arow = A + (size_t)(m0 + mm) * K;
            As[kk][mm] = (k < K) ? __ldg(&arow[k]) : 0.f;
        }
        // Stage B tile: 512 float4, 2/thread
#pragma unroll
        for (int i = 0; i < 2; i++) {
            int idx4 = tid + i * 256;
            int k2 = idx4 >> 5, n4 = idx4 & 31;
            int kg = k0 + k2;
            float4 v = make_float4(0.f, 0.f, 0.f, 0.f);
            if (kg < K) v = *(const float4*)&W[(size_t)kg * GATES + n0 + n4 * 4];
            *(float4*)&Bs[k2][n4 * 4] = v;
        }
        __syncthreads();
#pragma unroll
        for (int kk = 0; kk < BK; kk++) {
            ull ap[4];
#pragma unroll
            for (int ip = 0; ip < 4; ip++)
                ap[ip] = lds64(asadr + (unsigned)((kk * 132 + ty * 8 + ip * 2) * 4));
            float4 bq0 = *(const float4*)&Bs[kk][tx * 8];
            float4 bq1 = *(const float4*)&Bs[kk][tx * 8 + 4];
            ull bd[8];
            bd[0] = pack2(bq0.x, bq0.x); bd[1] = pack2(bq0.y, bq0.y);
            bd[2] = pack2(bq0.z, bq0.z); bd[3] = pack2(bq0.w, bq0.w);
            bd[4] = pack2(bq1.x, bq1.x); bd[5] = pack2(bq1.y, bq1.y);
            bd[6] = pack2(bq1.z, bq1.z); bd[7] = pack2(bq1.w, bq1.w);
#pragma unroll
            for (int ip = 0; ip < 4; ip++)
#pragma unroll
                for (int j = 0; j < 8; j++)
                    ffma2(acc[ip][j], ap[ip], bd[j]);
        }
        __syncthreads();
    }

    const float4 bv0 = *(const float4*)&bias[n0 + tx * 8];
    const float4 bv1 = *(const float4*)&bias[n0 + tx * 8 + 4];
#pragma unroll
    for (int ip = 0; ip < 4; ip++) {
        float2 u[8];
#pragma unroll
        for (int j = 0; j < 8; j++) u[j] = unpack2(acc[ip][j]);
        int m = m0 + ty * 8 + ip * 2;
        float* c0 = &C[(size_t)m * GATES + n0 + tx * 8];
        float* c1 = c0 + GATES;
        *(float4*)c0       = make_float4(u[0].x + bv0.x, u[1].x + bv0.y, u[2].x + bv0.z, u[3].x + bv0.w);
        *(float4*)(c0 + 4) = make_float4(u[4].x + bv1.x, u[5].x + bv1.y, u[6].x + bv1.z, u[7].x + bv1.w);
        *(float4*)c1       = make_float4(u[0].y + bv0.x, u[1].y + bv0.y, u[2].y + bv0.z, u[3].y + bv0.w);
        *(float4*)(c1 + 4) = make_float4(u[4].y + bv1.x, u[5].y + bv1.y, u[6].y + bv1.z, u[7].y + bv1.w);
    }
}

// ---------------------------------------------------------------------------
// Per-batch-group barrier: 32 CTAs sharing bg. Sense-reversing, self-resetting.
// __nanosleep in the spin keeps the poll rate (and L2 atomic pressure) low.
// ---------------------------------------------------------------------------
__device__ __forceinline__ void group_barrier(int bg, unsigned& local)
{
    __threadfence();
    __syncthreads();
    if (threadIdx.x == 0) {
        unsigned s = local ^ 1u;
        local = s;
        if (atomicAdd(&g_cnt4[bg], 1u) == 31u) {
            g_cnt4[bg] = 0;
            __threadfence();
            g_sense4[bg] = s;          // release
        } else {
            while (g_sense4[bg] != s) __nanosleep(32);
            __threadfence();
        }
    }
    __syncthreads();
}

// ---------------------------------------------------------------------------
// Persistent GRU scan. 128 CTAs x 256 threads (1 CTA/SM).
//   CTA c: bg = c>>5 (16 batches), jg = c&31 (16 h-columns).
//   Thread (cc=tid>>4, kc=tid&15): output (b = bg*16+kc, j = jg*16+cc);
//   U[3][32] for column j, k-chunk kc held in registers (f32x2).
//   Per step: accumulate 16 batch-partials in regs, scatter-reduce over kc
//   lanes (15 shfl/gate), gates, per-bg barrier, restage h; xg prefetched 1
//   step ahead.
// ---------------------------------------------------------------------------
__global__ void __launch_bounds__(256, 1) gru_scan(
    const float* __restrict__ U,      // [512][1536]
    const float* __restrict__ brec,   // recurrent bias b[1], length 1536
    const float* __restrict__ xg,     // [SEQ][BATCH][1536] (input proj + b[0])
    float* __restrict__ y,            // layer0: [s][b][512]; layer1: [b][s][512]
    float* __restrict__ hlast,        // layer1 only
    int layer)
{
    extern __shared__ float sm[];
    float* hs = sm;                   // 256 chunks * CHW = 8704 floats
    float* xs = sm + 256 * CHW;       // 16 * 50 = 800 floats

    const int tid = threadIdx.x;
    const int cc = tid >> 4;          // local column
    const int kc = tid & 15;          // k-chunk / owned local batch
    const int c = blockIdx.x;
    const int bg = c >> 5;
    const int jg = c & 31;
    const int jglob = jg * 16 + cc;
    const int bglob = bg * 16 + kc;

    // ---- Stage U into smem (coalesced), lift to registers ----
    {
        float* Ustage = sm;           // [48 cols][512 k]
        for (int i = tid; i < 512 * 64; i += 256) {
            int c64 = i & 63;
            if (c64 < 48) {
                int k = i >> 6;
                int g = c64 >> 4, c2 = c64 & 15;
                Ustage[c64 * 512 + k] = __ldg(&U[(size_t)k * GATES + g * UNITS + jg * 16 + c2]);
            }
        }
        __syncthreads();
    }
    ull uz[16], ur[16], uh[16];
    {
        const float* Ustage = sm;
        const int k0 = kc * 32;
#pragma unroll
        for (int i = 0; i < 16; i++) {
            uz[i] = pack2(Ustage[(0 * 16 + cc) * 512 + k0 + 2 * i],
                          Ustage[(0 * 16 + cc) * 512 + k0 + 2 * i + 1]);
            ur[i] = pack2(Ustage[(1 * 16 + cc) * 512 + k0 + 2 * i],
                          Ustage[(1 * 16 + cc) * 512 + k0 + 2 * i + 1]);
            uh[i] = pack2(Ustage[(2 * 16 + cc) * 512 + k0 + 2 * i],
                          Ustage[(2 * 16 + cc) * 512 + k0 + 2 * i + 1]);
        }
    }
    const float bz = brec[jglob];
    const float br = brec[UNITS + jglob];
    const float bh = brec[2 * UNITS + jglob];
    __syncthreads();

    // h0 = 0
    for (int i = tid; i < 256 * CHW; i += 256) hs[i] = 0.f;

    // Invariant xg prefetch mapping (3 elements/thread/step, coalesced)
    int xoff[3], xsi[3];
#pragma unroll
    for (int p = 0; p < 3; p++) {
        int idx = tid + p * 256;
        int b = idx / 48, ccol = idx - b * 48;
        int g = ccol >> 4, c2 = ccol & 15;
        xoff[p] = (bg * 16 + b) * GATES + g * UNITS + jg * 16 + c2;
        xsi[p]  = b * 50 + ccol;
    }
    float xpre[3];
#pragma unroll
    for (int p = 0; p < 3; p++) xpre[p] = __ldcg(&xg[xoff[p]]);   // t = 0

    unsigned local = g_sense4[bg];    // read before any group member can flip
    const unsigned hsaddr = smem_u32(hs);
    const bool bb0 = kc & 1, bb1 = kc & 2, bb2 = kc & 4, bb3 = kc & 8;
    float hold = 0.f;
    __syncthreads();

    for (int t = 0; t < SEQ; t++) {
        // Commit prefetched xg for this step
#pragma unroll
        for (int p = 0; p < 3; p++) xs[xsi[p]] = xpre[p];
        __syncthreads();              // xs ready; also orders last restage of hs

        // Accumulate partials for all 16 batches (chunk kc of each)
        float pz[16], pr[16], ph[16];
#pragma unroll
        for (int bl = 0; bl < 16; bl++) {
            const unsigned ha = hsaddr + (unsigned)((bl * 16 + kc) * (CHW * 4));
            ull az = 0ull, ar = 0ull, ah = 0ull;
#pragma unroll
            for (int i = 0; i < 16; i++) {
                ull hv = lds64(ha + (unsigned)(8 * i));
                ffma2(az, hv, uz[i]);
                ffma2(ar, hv, ur[i]);
                ffma2(ah, hv, uh[i]);
            }
            float2 a2 = unpack2(az); pz[bl] = a2.x + a2.y;
            float2 r2 = unpack2(ar); pr[bl] = r2.x + r2.y;
            float2 h2 = unpack2(ah); ph[bl] = h2.x + h2.y;
        }

        // Scatter-reduce over kc lanes: lane kc ends with sums for bl = kc
        float qz[8], qr[8], qh[8];
#pragma unroll
        for (int i = 0; i < 8; i++) {
            qz[i] = red_step(pz[2 * i], pz[2 * i + 1], bb0, 1);
            qr[i] = red_step(pr[2 * i], pr[2 * i + 1], bb0, 1);
            qh[i] = red_step(ph[2 * i], ph[2 * i + 1], bb0, 1);
        }
        float rz[4], rr[4], rh[4];
#pragma unroll
        for (int i = 0; i < 4; i++) {
            rz[i] = red_step(qz[2 * i], qz[2 * i + 1], bb1, 2);
            rr[i] = red_step(qr[2 * i], qr[2 * i + 1], bb1, 2);
            rh[i] = red_step(qh[2 * i], qh[2 * i + 1], bb1, 2);
        }
        float sz[2], sr[2], sh[2];
#pragma unroll
        for (int i = 0; i < 2; i++) {
            sz[i] = red_step(rz[2 * i], rz[2 * i + 1], bb2, 4);
            sr[i] = red_step(rr[2 * i], rr[2 * i + 1], bb2, 4);
            sh[i] = red_step(rh[2 * i], rh[2 * i + 1], bb2, 4);
        }
        const float AZ = red_step(sz[0], sz[1], bb3, 8);
        const float AR = red_step(sr[0], sr[1], bb3, 8);
        const float AH = red_step(sh[0], sh[1], bb3, 8);

        // Gate math (fast transcendentals; rel err ~1e-6)
        const float xz = xs[kc * 50 + cc];
        const float xr = xs[kc * 50 + 16 + cc];
        const float xh = xs[kc * 50 + 32 + cc];
        float z = __fdividef(1.f, 1.f + __expf(-(xz + AZ + bz)));
        float r = __fdividef(1.f, 1.f + __expf(-(xr + AR + br)));
        float pre = xh + r * (AH + bh);
        float hhat = 1.f - __fdividef(2.f, __expf(2.f * pre) + 1.f);  // tanh
        float hnew = z * hold + (1.f - z) * hhat;
        hold = hnew;

        const int nb = (t + 1) & 1;
        __stcg(&g_h[nb][bglob * UNITS + jglob], hnew);
        if (layer == 0) {
            __stcg(&y[((size_t)t * BATCH + bglob) * UNITS + jglob], hnew);
        } else {
            __stcg(&y[((size_t)bglob * SEQ + t) * UNITS + jglob], hnew);
            if (t == SEQ - 1) __stcg(&hlast[bglob * UNITS + jglob], hnew);
        }

        // Prefetch next step's xg (latency hidden behind barrier)
        if (t + 1 < SEQ) {
            const float* xb = xg + (size_t)(t + 1) * BATCH * GATES;
#pragma unroll
            for (int p = 0; p < 3; p++) xpre[p] = __ldcg(&xb[xoff[p]]);
        }

        group_barrier(bg, local);

        // Restage h for next step (L2; written by same-bg peers)
        {
            const float2* gsrc = (const float2*)(&g_h[nb][bg * 16 * UNITS]);
#pragma unroll
            for (int p = 0; p < 16; p++) {
                int e2 = tid + p * 256;
                int b = e2 >> 8, kp = e2 & 255;
                float2 v = __ldcg(&gsrc[e2]);
                *(float2*)(hs + (b * 16 + (kp >> 4)) * CHW + (kp & 15) * 2) = v;
            }
        }
        // next iteration's __syncthreads orders hs
    }
}

// ---------------------------------------------------------------------------
// Launch
// ---------------------------------------------------------------------------
extern "C" void kernel_launch(void* const* d_in, const int* in_sizes, int n_in,
                              void* d_out, int out_size)
{
    const int*   tokens = (const int*)d_in[0];
    const float* emb    = (const float*)d_in[1];
    const float* W0     = (const float*)d_in[2];
    const float* U0     = (const float*)d_in[3];
    const float* b0     = (const float*)d_in[4];
    const float* W1     = (const float*)d_in[5];
    const float* U1     = (const float*)d_in[6];
    const float* b1     = (const float*)d_in[7];

    float* out = (float*)d_out;
    float* y1  = out;                                    // [64][512][512]
    float* h1  = out + (size_t)BATCH * SEQ * UNITS;      // [64][512]

    float *xgp, *y0p;
    cudaGetSymbolAddress((void**)&xgp, g_xg);
    cudaGetSymbolAddress((void**)&y0p, g_y0);

    const int smem_scan = 48 * 512 * (int)sizeof(float); // 96 KB (U staging; >= hs+xs)
    cudaFuncSetAttribute(gru_scan, cudaFuncAttributeMaxDynamicSharedMemorySize, smem_scan);

    dim3 ggrid(GATES / BN, (SEQ * BATCH) / BM);          // (12, 256)

    // Layer 0: xg = gather(emb, tokens) @ W0 + b0[0]
    gemm_bias<<<ggrid, 256>>>(nullptr, tokens, emb, W0, b0, xgp, HIDDEN, 1);
    // Layer 0 scan -> y0 [s][b][u]
    gru_scan<<<NBLK, 256, smem_scan>>>(U0, b0 + GATES, xgp, y0p, nullptr, 0);
    // Layer 1: xg = y0 @ W1 + b1[0]
    gemm_bias<<<ggrid, 256>>>(y0p, nullptr, nullptr, W1, b1, xgp, UNITS, 0);
    // Layer 1 scan -> y1 [b][s][u], h1
    gru_scan<<<NBLK, 256, smem_scan>>>(U1, b1 + GATES, xgp, y1, h1, 1);
}

// round 8
// speedup vs baseline: 1.5467x; 1.0925x over previous
#include <cuda_runtime.h>
#include <math.h>
#include <stdint.h>

#define BATCH 64
#define SEQ   512
#define HIDDEN 300
#define UNITS 512
#define GATES 1536           // 3 * UNITS, gate order [z, r, h]

#define NBLK 128             // scan grid size (all CTAs co-resident)
#define CHW  34              // floats per 32-k h chunk (136B, 8B-aligned, bank-skewed)

typedef unsigned long long ull;

// ---------------------------------------------------------------------------
// Packed f32x2 helpers (sm_100+: FFMA2)
// ---------------------------------------------------------------------------
__device__ __forceinline__ void ffma2(ull& d, ull a, ull b) {
    asm("fma.rn.f32x2 %0, %1, %2, %0;" : "+l"(d) : "l"(a), "l"(b));
}
__device__ __forceinline__ ull pack2(float x, float y) {
    ull r; asm("mov.b64 %0, {%1, %2};" : "=l"(r) : "f"(x), "f"(y)); return r;
}
__device__ __forceinline__ float2 unpack2(ull v) {
    float2 r; asm("mov.b64 {%0, %1}, %2;" : "=f"(r.x), "=f"(r.y) : "l"(v)); return r;
}
__device__ __forceinline__ ull lds64(unsigned addr) {
    ull r; asm volatile("ld.shared.b64 %0, [%1];" : "=l"(r) : "r"(addr)); return r;
}
__device__ __forceinline__ unsigned smem_u32(const void* p) {
    return (unsigned)__cvta_generic_to_shared(p);
}
// One scatter-reduce step: lane keeps the slot matching its kc bit, sends the
// other; the single shfl serves both directions of the pair.
__device__ __forceinline__ float red_step(float e, float o, bool bit, int m) {
    float send = bit ? e : o;
    float keep = bit ? o : e;
    return keep + __shfl_xor_sync(0xffffffffu, send, m);
}

// ---------------------------------------------------------------------------
// Scratch (device globals; no allocations allowed)
// ---------------------------------------------------------------------------
__device__ float g_xg[(size_t)SEQ * BATCH * GATES];   // 201 MB, reused by both layers
__device__ float g_y0[(size_t)SEQ * BATCH * UNITS];   // 67 MB, layer0 outputs [s][b][u]
__device__ float g_h[2][BATCH * UNITS];               // double-buffered hidden state
__device__ unsigned g_cnt4[4];                        // per-bg barrier counters
__device__ volatile unsigned g_sense4[4];             // per-bg senses (self-restoring)

// ---------------------------------------------------------------------------
// GEMM: C[m][n] = sum_k A[m][k] * W[k][n] + bias[n]
//   m = s*64 + b (32768 rows), n in [0,1536). BM=128, BN=128, BK=16.
//   Thread tile 8x8 as 4 M-pairs (f32x2) x 8 N.
//   DOUBLE-BUFFERED: tile kt+1 prefetched into registers while computing kt.
// ---------------------------------------------------------------------------
#define BM 128
#define BN 128
#define BK 16
__global__ void __launch_bounds__(256, 2) gemm_bias(
    const float* __restrict__ A, const int* __restrict__ tokens,
    const float* __restrict__ emb, const float* __restrict__ W,
    const float* __restrict__ bias, float* __restrict__ C,
    int K, int gather)
{
    __shared__ float As[2][BK][132];   // [stage][k][m] padded
    __shared__ float Bs[2][BK][BN];    // [stage][k][n]
    __shared__ int   stok[BM];

    const int tid = threadIdx.x;
    const int tx = tid & 15;        // 8 cols: n0 + tx*8 ..
    const int ty = tid >> 4;        // 8 rows: m0 + ty*8 ..
    const int m0 = blockIdx.y * BM;
    const int n0 = blockIdx.x * BN;

    if (gather && tid < BM) {
        int m = m0 + tid;
        stok[tid] = __ldg(&tokens[(m & 63) * SEQ + (m >> 6)]);
    }
    __syncthreads();

    ull acc[4][8];
#pragma unroll
    for (int i = 0; i < 4; i++)
#pragma unroll
        for (int j = 0; j < 8; j++) acc[i][j] = 0ull;

    float  areg[8];
    float4 breg[2];

    // gmem -> registers for tile kt
    auto load_tile = [&](int kt) {
        const int k0 = kt * BK;
#pragma unroll
        for (int i = 0; i < 8; i++) {
            int idx = tid + i * 256;
            int mm = idx >> 4, kk = idx & 15;
            int k = k0 + kk;
            const float* arow;
            if (gather) arow = emb + (size_t)stok[mm] * HIDDEN;
            else        arow = A + (size_t)(m0 + mm) * K;
            areg[i] = (k < K) ? __ldg(&arow[k]) : 0.f;
        }
#pragma unroll
        for (int i = 0; i < 2; i++) {
            int idx4 = tid + i * 256;
            int k2 = idx4 >> 5, n4 = idx4 & 31;
            int kg = k0 + k2;
            breg[i] = (kg < K) ? *(const float4*)&W[(size_t)kg * GATES + n0 + n4 * 4]
                               : make_float4(0.f, 0.f, 0.f, 0.f);
        }
    };
    // registers -> smem stage st
    auto store_tile = [&](int st) {
#pragma unroll
        for (int i = 0; i < 8; i++) {
            int idx = tid + i * 256;
            As[st][idx & 15][idx >> 4] = areg[i];
        }
#pragma unroll
        for (int i = 0; i < 2; i++) {
            int idx4 = tid + i * 256;
            *(float4*)&Bs[st][idx4 >> 5][(idx4 & 31) * 4] = breg[i];
        }
    };

    const unsigned asadr = smem_u32(&As[0][0][0]);
    const unsigned asstride = (unsigned)(BK * 132 * 4);   // bytes per stage

    const int ntiles = (K + BK - 1) / BK;
    load_tile(0);
    store_tile(0);
    __syncthreads();

    for (int kt = 0; kt < ntiles; kt++) {
        const int cur = kt & 1;
        if (kt + 1 < ntiles) load_tile(kt + 1);   // LDGs in flight during compute

        const unsigned abase = asadr + (unsigned)cur * asstride;
#pragma unroll
        for (int kk = 0; kk < BK; kk++) {
            ull ap[4];
#pragma unroll
            for (int ip = 0; ip < 4; ip++)
                ap[ip] = lds64(abase + (unsigned)((kk * 132 + ty * 8 + ip * 2) * 4));
            float4 bq0 = *(const float4*)&Bs[cur][kk][tx * 8];
            float4 bq1 = *(const float4*)&Bs[cur][kk][tx * 8 + 4];
            ull bd[8];
            bd[0] = pack2(bq0.x, bq0.x); bd[1] = pack2(bq0.y, bq0.y);
            bd[2] = pack2(bq0.z, bq0.z); bd[3] = pack2(bq0.w, bq0.w);
            bd[4] = pack2(bq1.x, bq1.x); bd[5] = pack2(bq1.y, bq1.y);
            bd[6] = pack2(bq1.z, bq1.z); bd[7] = pack2(bq1.w, bq1.w);
#pragma unroll
            for (int ip = 0; ip < 4; ip++)
#pragma unroll
                for (int j = 0; j < 8; j++)
                    ffma2(acc[ip][j], ap[ip], bd[j]);
        }

        if (kt + 1 < ntiles) store_tile((kt + 1) & 1);   // other stage: no race
        __syncthreads();
    }

    const float4 bv0 = *(const float4*)&bias[n0 + tx * 8];
    const float4 bv1 = *(const float4*)&bias[n0 + tx * 8 + 4];
#pragma unroll
    for (int ip = 0; ip < 4; ip++) {
        float2 u[8];
#pragma unroll
        for (int j = 0; j < 8; j++) u[j] = unpack2(acc[ip][j]);
        int m = m0 + ty * 8 + ip * 2;
        float* c0 = &C[(size_t)m * GATES + n0 + tx * 8];
        float* c1 = c0 + GATES;
        *(float4*)c0       = make_float4(u[0].x + bv0.x, u[1].x + bv0.y, u[2].x + bv0.z, u[3].x + bv0.w);
        *(float4*)(c0 + 4) = make_float4(u[4].x + bv1.x, u[5].x + bv1.y, u[6].x + bv1.z, u[7].x + bv1.w);
        *(float4*)c1       = make_float4(u[0].y + bv0.x, u[1].y + bv0.y, u[2].y + bv0.z, u[3].y + bv0.w);
        *(float4*)(c1 + 4) = make_float4(u[4].y + bv1.x, u[5].y + bv1.y, u[6].y + bv1.z, u[7].y + bv1.w);
    }
}

// ---------------------------------------------------------------------------
// Per-batch-group barrier: 32 CTAs sharing bg. Sense-reversing, self-resetting.
// __nanosleep in the spin keeps the poll rate (and L2 atomic pressure) low.
// ---------------------------------------------------------------------------
__device__ __forceinline__ void group_barrier(int bg, unsigned& local)
{
    __threadfence();
    __syncthreads();
    if (threadIdx.x == 0) {
        unsigned s = local ^ 1u;
        local = s;
        if (atomicAdd(&g_cnt4[bg], 1u) == 31u) {
            g_cnt4[bg] = 0;
            __threadfence();
            g_sense4[bg] = s;          // release
        } else {
            while (g_sense4[bg] != s) __nanosleep(32);
            __threadfence();
        }
    }
    __syncthreads();
}

// ---------------------------------------------------------------------------
// Persistent GRU scan. 128 CTAs x 256 threads (1 CTA/SM).
//   CTA c: bg = c>>5 (16 batches), jg = c&31 (16 h-columns).
//   Thread (cc=tid>>4, kc=tid&15): output (b = bg*16+kc, j = jg*16+cc);
//   U[3][32] for column j, k-chunk kc held in registers (f32x2).
//   Per step: accumulate 16 batch-partials in regs, scatter-reduce over kc
//   lanes (15 shfl/gate), gates, per-bg barrier, restage h; xg prefetched 1
//   step ahead.
// ---------------------------------------------------------------------------
__global__ void __launch_bounds__(256, 1) gru_scan(
    const float* __restrict__ U,      // [512][1536]
    const float* __restrict__ brec,   // recurrent bias b[1], length 1536
    const float* __restrict__ xg,     // [SEQ][BATCH][1536] (input proj + b[0])
    float* __restrict__ y,            // layer0: [s][b][512]; layer1: [b][s][512]
    float* __restrict__ hlast,        // layer1 only
    int layer)
{
    extern __shared__ float sm[];
    float* hs = sm;                   // 256 chunks * CHW = 8704 floats
    float* xs = sm + 256 * CHW;       // 16 * 50 = 800 floats

    const int tid = threadIdx.x;
    const int cc = tid >> 4;          // local column
    const int kc = tid & 15;          // k-chunk / owned local batch
    const int c = blockIdx.x;
    const int bg = c >> 5;
    const int jg = c & 31;
    const int jglob = jg * 16 + cc;
    const int bglob = bg * 16 + kc;

    // ---- Stage U into smem (coalesced), lift to registers ----
    {
        float* Ustage = sm;           // [48 cols][512 k]
        for (int i = tid; i < 512 * 64; i += 256) {
            int c64 = i & 63;
            if (c64 < 48) {
                int k = i >> 6;
                int g = c64 >> 4, c2 = c64 & 15;
                Ustage[c64 * 512 + k] = __ldg(&U[(size_t)k * GATES + g * UNITS + jg * 16 + c2]);
            }
        }
        __syncthreads();
    }
    ull uz[16], ur[16], uh[16];
    {
        const float* Ustage = sm;
        const int k0 = kc * 32;
#pragma unroll
        for (int i = 0; i < 16; i++) {
            uz[i] = pack2(Ustage[(0 * 16 + cc) * 512 + k0 + 2 * i],
                          Ustage[(0 * 16 + cc) * 512 + k0 + 2 * i + 1]);
            ur[i] = pack2(Ustage[(1 * 16 + cc) * 512 + k0 + 2 * i],
                          Ustage[(1 * 16 + cc) * 512 + k0 + 2 * i + 1]);
            uh[i] = pack2(Ustage[(2 * 16 + cc) * 512 + k0 + 2 * i],
                          Ustage[(2 * 16 + cc) * 512 + k0 + 2 * i + 1]);
        }
    }
    const float bz = brec[jglob];
    const float br = brec[UNITS + jglob];
    const float bh = brec[2 * UNITS + jglob];
    __syncthreads();

    // h0 = 0
    for (int i = tid; i < 256 * CHW; i += 256) hs[i] = 0.f;

    // Invariant xg prefetch mapping (3 elements/thread/step, coalesced)
    int xoff[3], xsi[3];
#pragma unroll
    for (int p = 0; p < 3; p++) {
        int idx = tid + p * 256;
        int b = idx / 48, ccol = idx - b * 48;
        int g = ccol >> 4, c2 = ccol & 15;
        xoff[p] = (bg * 16 + b) * GATES + g * UNITS + jg * 16 + c2;
        xsi[p]  = b * 50 + ccol;
    }
    float xpre[3];
#pragma unroll
    for (int p = 0; p < 3; p++) xpre[p] = __ldcg(&xg[xoff[p]]);   // t = 0

    unsigned local = g_sense4[bg];    // read before any group member can flip
    const unsigned hsaddr = smem_u32(hs);
    const bool bb0 = kc & 1, bb1 = kc & 2, bb2 = kc & 4, bb3 = kc & 8;
    float hold = 0.f;
    __syncthreads();

    for (int t = 0; t < SEQ; t++) {
        // Commit prefetched xg for this step
#pragma unroll
        for (int p = 0; p < 3; p++) xs[xsi[p]] = xpre[p];
        __syncthreads();              // xs ready; also orders last restage of hs

        // Accumulate partials for all 16 batches (chunk kc of each)
        float pz[16], pr[16], ph[16];
#pragma unroll
        for (int bl = 0; bl < 16; bl++) {
            const unsigned ha = hsaddr + (unsigned)((bl * 16 + kc) * (CHW * 4));
            ull az = 0ull, ar = 0ull, ah = 0ull;
#pragma unroll
            for (int i = 0; i < 16; i++) {
                ull hv = lds64(ha + (unsigned)(8 * i));
                ffma2(az, hv, uz[i]);
                ffma2(ar, hv, ur[i]);
                ffma2(ah, hv, uh[i]);
            }
            float2 a2 = unpack2(az); pz[bl] = a2.x + a2.y;
            float2 r2 = unpack2(ar); pr[bl] = r2.x + r2.y;
            float2 h2 = unpack2(ah); ph[bl] = h2.x + h2.y;
        }

        // Scatter-reduce over kc lanes: lane kc ends with sums for bl = kc
        float qz[8], qr[8], qh[8];
#pragma unroll
        for (int i = 0; i < 8; i++) {
            qz[i] = red_step(pz[2 * i], pz[2 * i + 1], bb0, 1);
            qr[i] = red_step(pr[2 * i], pr[2 * i + 1], bb0, 1);
            qh[i] = red_step(ph[2 * i], ph[2 * i + 1], bb0, 1);
        }
        float rz[4], rr[4], rh[4];
#pragma unroll
        for (int i = 0; i < 4; i++) {
            rz[i] = red_step(qz[2 * i], qz[2 * i + 1], bb1, 2);
            rr[i] = red_step(qr[2 * i], qr[2 * i + 1], bb1, 2);
            rh[i] = red_step(qh[2 * i], qh[2 * i + 1], bb1, 2);
        }
        float sz[2], sr[2], sh[2];
#pragma unroll
        for (int i = 0; i < 2; i++) {
            sz[i] = red_step(rz[2 * i], rz[2 * i + 1], bb2, 4);
            sr[i] = red_step(rr[2 * i], rr[2 * i + 1], bb2, 4);
            sh[i] = red_step(rh[2 * i], rh[2 * i + 1], bb2, 4);
        }
        const float AZ = red_step(sz[0], sz[1], bb3, 8);
        const float AR = red_step(sr[0], sr[1], bb3, 8);
        const float AH = red_step(sh[0], sh[1], bb3, 8);

        // Gate math (fast transcendentals; rel err ~1e-6)
        const float xz = xs[kc * 50 + cc];
        const float xr = xs[kc * 50 + 16 + cc];
        const float xh = xs[kc * 50 + 32 + cc];
        float z = __fdividef(1.f, 1.f + __expf(-(xz + AZ + bz)));
        float r = __fdividef(1.f, 1.f + __expf(-(xr + AR + br)));
        float pre = xh + r * (AH + bh);
        float hhat = 1.f - __fdividef(2.f, __expf(2.f * pre) + 1.f);  // tanh
        float hnew = z * hold + (1.f - z) * hhat;
        hold = hnew;

        const int nb = (t + 1) & 1;
        __stcg(&g_h[nb][bglob * UNITS + jglob], hnew);
        if (layer == 0) {
            __stcg(&y[((size_t)t * BATCH + bglob) * UNITS + jglob], hnew);
        } else {
            __stcg(&y[((size_t)bglob * SEQ + t) * UNITS + jglob], hnew);
            if (t == SEQ - 1) __stcg(&hlast[bglob * UNITS + jglob], hnew);
        }

        // Prefetch next step's xg (latency hidden behind barrier)
        if (t + 1 < SEQ) {
            const float* xb = xg + (size_t)(t + 1) * BATCH * GATES;
#pragma unroll
            for (int p = 0; p < 3; p++) xpre[p] = __ldcg(&xb[xoff[p]]);
        }

        group_barrier(bg, local);

        // Restage h for next step (L2; written by same-bg peers)
        {
            const float2* gsrc = (const float2*)(&g_h[nb][bg * 16 * UNITS]);
#pragma unroll
            for (int p = 0; p < 16; p++) {
                int e2 = tid + p * 256;
                int b = e2 >> 8, kp = e2 & 255;
                float2 v = __ldcg(&gsrc[e2]);
                *(float2*)(hs + (b * 16 + (kp >> 4)) * CHW + (kp & 15) * 2) = v;
            }
        }
        // next iteration's __syncthreads orders hs
    }
}

// ---------------------------------------------------------------------------
// Launch
// ---------------------------------------------------------------------------
extern "C" void kernel_launch(void* const* d_in, const int* in_sizes, int n_in,
                              void* d_out, int out_size)
{
    const int*   tokens = (const int*)d_in[0];
    const float* emb    = (const float*)d_in[1];
    const float* W0     = (const float*)d_in[2];
    const float* U0     = (const float*)d_in[3];
    const float* b0     = (const float*)d_in[4];
    const float* W1     = (const float*)d_in[5];
    const float* U1     = (const float*)d_in[6];
    const float* b1     = (const float*)d_in[7];

    float* out = (float*)d_out;
    float* y1  = out;                                    // [64][512][512]
    float* h1  = out + (size_t)BATCH * SEQ * UNITS;      // [64][512]

    float *xgp, *y0p;
    cudaGetSymbolAddress((void**)&xgp, g_xg);
    cudaGetSymbolAddress((void**)&y0p, g_y0);

    const int smem_scan = 48 * 512 * (int)sizeof(float); // 96 KB (U staging; >= hs+xs)
    cudaFuncSetAttribute(gru_scan, cudaFuncAttributeMaxDynamicSharedMemorySize, smem_scan);

    dim3 ggrid(GATES / BN, (SEQ * BATCH) / BM);          // (12, 256)

    // Layer 0: xg = gather(emb, tokens) @ W0 + b0[0]
    gemm_bias<<<ggrid, 256>>>(nullptr, tokens, emb, W0, b0, xgp, HIDDEN, 1);
    // Layer 0 scan -> y0 [s][b][u]
    gru_scan<<<NBLK, 256, smem_scan>>>(U0, b0 + GATES, xgp, y0p, nullptr, 0);
    // Layer 1: xg = y0 @ W1 + b1[0]
    gemm_bias<<<ggrid, 256>>>(y0p, nullptr, nullptr, W1, b1, xgp, UNITS, 0);
    // Layer 1 scan -> y1 [b][s][u], h1
    gru_scan<<<NBLK, 256, smem_scan>>>(U1, b1 + GATES, xgp, y1, h1, 1);
}